// round 1
// baseline (speedup 1.0000x reference)
#include <cuda_runtime.h>

// Problem constants (fixed by the dataset)
#define NMAX 50000
#define EMAX 800000

// ---------------- device scratch (module-static, no runtime allocs) ----------
__device__ float g_h1[NMAX * 128];     // layer1 projected features  [N,8,16]
__device__ float g_als1[NMAX * 8];     // alpha_src logits layer1    [N,8]
__device__ float g_ald1[NMAX * 8];     // alpha_dst logits layer1    [N,8]
__device__ float g_hl2[NMAX * 128];    // layer1 output (relu) = layer2 input
__device__ float g_h2[NMAX * 16];      // layer2 projected features  [N,16]
__device__ float g_als2[NMAX];
__device__ float g_ald2[NMAX];
__device__ int   g_deg[NMAX];
__device__ int   g_off[NMAX + 1];
__device__ int   g_pos[NMAX];
__device__ int   g_csr[EMAX + NMAX];   // incoming-edge source lists (incl self loops)

// ---------------- CSR build --------------------------------------------------
__global__ void k_deginit(int n) {
    int i = blockIdx.x * blockDim.x + threadIdx.x;
    if (i < n) g_deg[i] = 1;  // self loop
}

__global__ void k_count(const int* __restrict__ dst, int E) {
    int i = blockIdx.x * blockDim.x + threadIdx.x;
    if (i < E) atomicAdd(&g_deg[dst[i]], 1);
}

// single-block exclusive scan of g_deg -> g_off (and g_pos copy)
__global__ void k_scan(int n) {
    __shared__ int sm[1024];
    int t = threadIdx.x;
    int chunk = (n + 1023) >> 10;
    int beg = t * chunk;
    int end = min(beg + chunk, n);
    int s = 0;
    for (int i = beg; i < end; i++) s += g_deg[i];
    sm[t] = s;
    __syncthreads();
    for (int off = 1; off < 1024; off <<= 1) {
        int v = (t >= off) ? sm[t - off] : 0;
        __syncthreads();
        sm[t] += v;
        __syncthreads();
    }
    int run = sm[t] - s;  // exclusive prefix for this chunk
    for (int i = beg; i < end; i++) {
        g_off[i] = run;
        g_pos[i] = run;
        run += g_deg[i];
    }
    if (t == 1023) g_off[n] = sm[1023];
}

__global__ void k_scatter(const int* __restrict__ src, const int* __restrict__ dst,
                          int E, int n) {
    int i = blockIdx.x * blockDim.x + threadIdx.x;
    if (i < E) {
        int d = dst[i];
        int p = atomicAdd(&g_pos[d], 1);
        g_csr[p] = src[i];
    } else if (i < E + n) {
        int d = i - E;
        int p = atomicAdd(&g_pos[d], 1);
        g_csr[p] = d;  // self loop
    }
}

// ---------------- GEMM1: h1 = x @ W1, plus attention logits ------------------
// block: 256 threads, 32 rows per block. thread = (rg 0..7, cg 0..31):
// 4 rows x 4 cols per thread. W streamed from gmem (L1-hot), x tile in smem.
__global__ void k_gemm1(const float* __restrict__ x, const float* __restrict__ W,
                        const float* __restrict__ as, const float* __restrict__ ad,
                        int n) {
    __shared__ float xs[32 * 128];
    int tid = threadIdx.x;
    int base = blockIdx.x * 32;
    const float4* xg = (const float4*)x;
    int lim = n * 32;  // float4 count
    for (int i = tid; i < 1024; i += 256) {
        int gi = base * 32 + i;
        float4 v = (gi < lim) ? xg[gi] : make_float4(0.f, 0.f, 0.f, 0.f);
        ((float4*)xs)[i] = v;
    }
    __syncthreads();

    int cg = tid & 31;
    int rg = tid >> 5;
    float acc[4][4];
#pragma unroll
    for (int r = 0; r < 4; r++)
#pragma unroll
        for (int j = 0; j < 4; j++) acc[r][j] = 0.f;

    const float4* W4 = (const float4*)W;
#pragma unroll 4
    for (int k = 0; k < 128; k++) {
        float4 w = __ldg(&W4[k * 32 + cg]);
#pragma unroll
        for (int r = 0; r < 4; r++) {
            float xv = xs[(rg * 4 + r) * 128 + k];
            acc[r][0] = fmaf(xv, w.x, acc[r][0]);
            acc[r][1] = fmaf(xv, w.y, acc[r][1]);
            acc[r][2] = fmaf(xv, w.z, acc[r][2]);
            acc[r][3] = fmaf(xv, w.w, acc[r][3]);
        }
    }

    float4 av = __ldg(&((const float4*)as)[cg]);
    float4 dv = __ldg(&((const float4*)ad)[cg]);
#pragma unroll
    for (int r = 0; r < 4; r++) {
        int row = base + rg * 4 + r;
        float ps = acc[r][0] * av.x + acc[r][1] * av.y + acc[r][2] * av.z + acc[r][3] * av.w;
        float pd = acc[r][0] * dv.x + acc[r][1] * dv.y + acc[r][2] * dv.z + acc[r][3] * dv.w;
        // reduce over the 4 lanes that share a head (16 channels)
        ps += __shfl_xor_sync(0xffffffffu, ps, 1);
        ps += __shfl_xor_sync(0xffffffffu, ps, 2);
        pd += __shfl_xor_sync(0xffffffffu, pd, 1);
        pd += __shfl_xor_sync(0xffffffffu, pd, 2);
        if (row < n) {
            ((float4*)g_h1)[row * 32 + cg] =
                make_float4(acc[r][0], acc[r][1], acc[r][2], acc[r][3]);
            if ((cg & 3) == 0) {
                g_als1[row * 8 + (cg >> 2)] = ps;
                g_ald1[row * 8 + (cg >> 2)] = pd;
            }
        }
    }
}

// ---------------- Edge pass layer1: warp per dst node ------------------------
__global__ void k_edge1(const float* __restrict__ b1, int n) {
    int gid = blockIdx.x * blockDim.x + threadIdx.x;
    int d = gid >> 5;
    int lane = gid & 31;
    if (d >= n) return;
    int head = lane >> 2;
    float ald = g_ald1[d * 8 + head];
    int beg = g_off[d], end = g_off[d + 1];
    float4 acc = make_float4(0.f, 0.f, 0.f, 0.f);
    float den = 0.f;
    for (int e = beg; e < end; e++) {
        int s = g_csr[e];
        float als = g_als1[s * 8 + head];
        float t = als + ald;
        t = t > 0.f ? t : 0.2f * t;  // leaky relu, slope 0.2
        float ex = __expf(t);
        float4 hv = ((const float4*)g_h1)[s * 32 + lane];
        acc.x = fmaf(ex, hv.x, acc.x);
        acc.y = fmaf(ex, hv.y, acc.y);
        acc.z = fmaf(ex, hv.z, acc.z);
        acc.w = fmaf(ex, hv.w, acc.w);
        den += ex;
    }
    float inv = 1.f / den;
    float4 b = ((const float4*)b1)[lane];
    float4 o;
    o.x = fmaxf(acc.x * inv + b.x, 0.f);
    o.y = fmaxf(acc.y * inv + b.y, 0.f);
    o.z = fmaxf(acc.z * inv + b.z, 0.f);
    o.w = fmaxf(acc.w * inv + b.w, 0.f);
    ((float4*)g_hl2)[d * 32 + lane] = o;
}

// ---------------- GEMM2: h2 = hl2 @ W2, plus logits --------------------------
// block 256 threads, 64 rows per block in 4 passes of 16 rows.
// thread = (rrg 0..15, col 0..15).
__global__ void k_gemm2(const float* __restrict__ W, const float* __restrict__ as,
                        const float* __restrict__ ad, int n) {
    __shared__ float ws[2048];
    __shared__ float xs[16 * 128];
    int tid = threadIdx.x;
    for (int i = tid; i < 2048; i += 256) ws[i] = W[i];
    int col = tid & 15;
    int rrg = tid >> 4;
    int base = blockIdx.x * 64;
    float as_c = __ldg(&as[col]);
    float ad_c = __ldg(&ad[col]);
    int lim = n * 32;
    for (int pass = 0; pass < 4; pass++) {
        int rb = base + pass * 16;
        __syncthreads();
        for (int i = tid; i < 512; i += 256) {
            int gi = rb * 32 + i;
            ((float4*)xs)[i] = (gi < lim) ? ((const float4*)g_hl2)[gi]
                                          : make_float4(0.f, 0.f, 0.f, 0.f);
        }
        __syncthreads();
        float acc = 0.f;
#pragma unroll 8
        for (int k = 0; k < 128; k++) acc = fmaf(xs[rrg * 128 + k], ws[k * 16 + col], acc);
        float ps = acc * as_c, pd = acc * ad_c;
        ps += __shfl_xor_sync(0xffffffffu, ps, 1);
        ps += __shfl_xor_sync(0xffffffffu, ps, 2);
        ps += __shfl_xor_sync(0xffffffffu, ps, 4);
        ps += __shfl_xor_sync(0xffffffffu, ps, 8);
        pd += __shfl_xor_sync(0xffffffffu, pd, 1);
        pd += __shfl_xor_sync(0xffffffffu, pd, 2);
        pd += __shfl_xor_sync(0xffffffffu, pd, 4);
        pd += __shfl_xor_sync(0xffffffffu, pd, 8);
        int row = rb + rrg;
        if (row < n) {
            g_h2[row * 16 + col] = acc;
            if (col == 0) {
                g_als2[row] = ps;
                g_ald2[row] = pd;
            }
        }
    }
}

// ---------------- Edge pass layer2: 16 lanes per dst node --------------------
__global__ void k_edge2(const float* __restrict__ b2, float* __restrict__ out, int n) {
    int gid = blockIdx.x * blockDim.x + threadIdx.x;
    int node = gid >> 4;
    int lane = gid & 15;
    if (node >= n) return;
    float ald = g_ald2[node];
    int beg = g_off[node], end = g_off[node + 1];
    float acc = 0.f, den = 0.f;
    for (int e = beg; e < end; e++) {
        int s = g_csr[e];
        float als = g_als2[s];
        float t = als + ald;
        t = t > 0.f ? t : 0.2f * t;
        float ex = __expf(t);
        acc = fmaf(ex, g_h2[s * 16 + lane], acc);
        den += ex;
    }
    out[node * 16 + lane] = fmaxf(acc / den + b2[lane], 0.f);
}

// ---------------- launch -----------------------------------------------------
extern "C" void kernel_launch(void* const* d_in, const int* in_sizes, int n_in,
                              void* d_out, int out_size) {
    const float* x     = (const float*)d_in[0];
    const int*   ei    = (const int*)d_in[1];
    const float* W1    = (const float*)d_in[2];
    const float* asrc1 = (const float*)d_in[3];
    const float* adst1 = (const float*)d_in[4];
    const float* b1    = (const float*)d_in[5];
    const float* W2    = (const float*)d_in[6];
    const float* asrc2 = (const float*)d_in[7];
    const float* adst2 = (const float*)d_in[8];
    const float* b2    = (const float*)d_in[9];

    int n = in_sizes[0] / 128;
    int E = in_sizes[1] / 2;
    const int* src = ei;
    const int* dst = ei + E;

    // CSR build (per call; static graph but must be deterministic/stateless)
    k_deginit<<<(n + 255) / 256, 256>>>(n);
    k_count<<<(E + 255) / 256, 256>>>(dst, E);
    k_scan<<<1, 1024>>>(n);
    k_scatter<<<(E + n + 255) / 256, 256>>>(src, dst, E, n);

    // layer 1
    k_gemm1<<<(n + 31) / 32, 256>>>(x, W1, asrc1, adst1, n);
    k_edge1<<<(n * 32 + 255) / 256, 256>>>(b1, n);

    // layer 2
    k_gemm2<<<(n + 63) / 64, 256>>>(W2, asrc2, adst2, n);
    k_edge2<<<(n * 16 + 255) / 256, 256>>>(b2, (float*)d_out, n);
}

// round 2
// speedup vs baseline: 1.0667x; 1.0667x over previous
#include <cuda_runtime.h>
#include <cuda_fp16.h>

// Problem constants (fixed by the dataset)
#define NMAX 50000
#define EMAX 800000

// ---------------- device scratch (module-static, no runtime allocs) ----------
__device__ __half g_h1[NMAX * 128];    // layer1 projected features, fp16  [N,8,16]
__device__ float  g_als1[NMAX * 8];    // alpha_src logits layer1    [N,8]
__device__ float  g_ald1[NMAX * 8];    // alpha_dst logits layer1    [N,8]
__device__ float  g_hl2[NMAX * 128];   // layer1 output (relu) = layer2 input
__device__ __half g_h2[NMAX * 16];     // layer2 projected features, fp16  [N,16]
__device__ float  g_als2[NMAX];
__device__ float  g_ald2[NMAX];
__device__ int    g_deg[NMAX];
__device__ int    g_off[NMAX + 1];
__device__ int    g_pos[NMAX];
__device__ int    g_csr[EMAX + NMAX];  // incoming-edge source lists (incl self loops)

// ---------------- CSR build --------------------------------------------------
__global__ void k_deginit(int n) {
    int i = blockIdx.x * blockDim.x + threadIdx.x;
    if (i < n) g_deg[i] = 1;  // self loop
}

__global__ void k_count(const int* __restrict__ dst, int E) {
    int i = blockIdx.x * blockDim.x + threadIdx.x;
    if (i < E) atomicAdd(&g_deg[dst[i]], 1);
}

// single-block exclusive scan of g_deg -> g_off (and g_pos copy)
__global__ void k_scan(int n) {
    __shared__ int sm[1024];
    int t = threadIdx.x;
    int chunk = (n + 1023) >> 10;
    int beg = t * chunk;
    int end = min(beg + chunk, n);
    int s = 0;
    for (int i = beg; i < end; i++) s += g_deg[i];
    sm[t] = s;
    __syncthreads();
    for (int off = 1; off < 1024; off <<= 1) {
        int v = (t >= off) ? sm[t - off] : 0;
        __syncthreads();
        sm[t] += v;
        __syncthreads();
    }
    int run = sm[t] - s;  // exclusive prefix for this chunk
    for (int i = beg; i < end; i++) {
        g_off[i] = run;
        g_pos[i] = run;
        run += g_deg[i];
    }
    if (t == 1023) g_off[n] = sm[1023];
}

__global__ void k_scatter(const int* __restrict__ src, const int* __restrict__ dst,
                          int E, int n) {
    int i = blockIdx.x * blockDim.x + threadIdx.x;
    if (i < E) {
        int d = dst[i];
        int p = atomicAdd(&g_pos[d], 1);
        g_csr[p] = src[i];
    } else if (i < E + n) {
        int d = i - E;
        int p = atomicAdd(&g_pos[d], 1);
        g_csr[p] = d;  // self loop
    }
}

// ---------------- GEMM1: h1 = x @ W1 (fp16 out), plus attention logits -------
// block: 256 threads, 64 rows per block. thread = (rg 0..7, cg 0..31):
// 8 rows x 4 cols per thread. W streamed from gmem (L1-hot), x tile in smem.
__global__ void __launch_bounds__(256) k_gemm1(
        const float* __restrict__ x, const float* __restrict__ W,
        const float* __restrict__ as, const float* __restrict__ ad, int n) {
    __shared__ float xs[64 * 128];  // 32 KB
    int tid = threadIdx.x;
    int base = blockIdx.x * 64;
    const float4* xg = (const float4*)x;
    int lim = n * 32;  // float4 count
    for (int i = tid; i < 2048; i += 256) {
        int gi = base * 32 + i;
        float4 v = (gi < lim) ? xg[gi] : make_float4(0.f, 0.f, 0.f, 0.f);
        ((float4*)xs)[i] = v;
    }
    __syncthreads();

    int cg = tid & 31;
    int rg = tid >> 5;
    float acc[8][4];
#pragma unroll
    for (int r = 0; r < 8; r++)
#pragma unroll
        for (int j = 0; j < 4; j++) acc[r][j] = 0.f;

    const float4* W4 = (const float4*)W;
#pragma unroll 2
    for (int k = 0; k < 128; k++) {
        float4 w = __ldg(&W4[k * 32 + cg]);
#pragma unroll
        for (int r = 0; r < 8; r++) {
            float xv = xs[(rg * 8 + r) * 128 + k];
            acc[r][0] = fmaf(xv, w.x, acc[r][0]);
            acc[r][1] = fmaf(xv, w.y, acc[r][1]);
            acc[r][2] = fmaf(xv, w.z, acc[r][2]);
            acc[r][3] = fmaf(xv, w.w, acc[r][3]);
        }
    }

    float4 av = __ldg(&((const float4*)as)[cg]);
    float4 dv = __ldg(&((const float4*)ad)[cg]);
#pragma unroll
    for (int r = 0; r < 8; r++) {
        int row = base + rg * 8 + r;
        float ps = acc[r][0] * av.x + acc[r][1] * av.y + acc[r][2] * av.z + acc[r][3] * av.w;
        float pd = acc[r][0] * dv.x + acc[r][1] * dv.y + acc[r][2] * dv.z + acc[r][3] * dv.w;
        // reduce over the 4 lanes that share a head (16 channels)
        ps += __shfl_xor_sync(0xffffffffu, ps, 1);
        ps += __shfl_xor_sync(0xffffffffu, ps, 2);
        pd += __shfl_xor_sync(0xffffffffu, pd, 1);
        pd += __shfl_xor_sync(0xffffffffu, pd, 2);
        if (row < n) {
            __half2 p0 = __floats2half2_rn(acc[r][0], acc[r][1]);
            __half2 p1 = __floats2half2_rn(acc[r][2], acc[r][3]);
            uint2 u;
            u.x = *(unsigned*)&p0;
            u.y = *(unsigned*)&p1;
            ((uint2*)g_h1)[row * 32 + cg] = u;  // 8 bytes = 4 fp16 channels
            if ((cg & 3) == 0) {
                g_als1[row * 8 + (cg >> 2)] = ps;
                g_ald1[row * 8 + (cg >> 2)] = pd;
            }
        }
    }
}

// ---------------- Edge pass layer1: warp per dst node ------------------------
__device__ __forceinline__ void edge1_step(int s, int lane, int head, float ald,
                                           float4& acc, float& den) {
    float als = g_als1[s * 8 + head];
    float t = als + ald;
    t = t > 0.f ? t : 0.2f * t;  // leaky relu, slope 0.2
    float ex = __expf(t);
    uint2 v = ((const uint2*)g_h1)[s * 32 + lane];
    __half2 a = *(__half2*)&v.x;
    __half2 b = *(__half2*)&v.y;
    float2 fa = __half22float2(a);
    float2 fb = __half22float2(b);
    acc.x = fmaf(ex, fa.x, acc.x);
    acc.y = fmaf(ex, fa.y, acc.y);
    acc.z = fmaf(ex, fb.x, acc.z);
    acc.w = fmaf(ex, fb.y, acc.w);
    den += ex;
}

__global__ void k_edge1(const float* __restrict__ b1, int n) {
    int gid = blockIdx.x * blockDim.x + threadIdx.x;
    int d = gid >> 5;
    int lane = gid & 31;
    if (d >= n) return;
    int head = lane >> 2;
    float ald = g_ald1[d * 8 + head];
    int beg = g_off[d], end = g_off[d + 1];
    float4 acc = make_float4(0.f, 0.f, 0.f, 0.f);
    float den = 0.f;
    int e = beg;
    for (; e + 1 < end; e += 2) {  // 2x unroll for MLP
        int s0 = g_csr[e];
        int s1 = g_csr[e + 1];
        edge1_step(s0, lane, head, ald, acc, den);
        edge1_step(s1, lane, head, ald, acc, den);
    }
    if (e < end) edge1_step(g_csr[e], lane, head, ald, acc, den);

    float inv = 1.f / den;
    float4 b = ((const float4*)b1)[lane];
    float4 o;
    o.x = fmaxf(acc.x * inv + b.x, 0.f);
    o.y = fmaxf(acc.y * inv + b.y, 0.f);
    o.z = fmaxf(acc.z * inv + b.z, 0.f);
    o.w = fmaxf(acc.w * inv + b.w, 0.f);
    ((float4*)g_hl2)[d * 32 + lane] = o;
}

// ---------------- GEMM2: h2 = hl2 @ W2 (fp16 out), plus logits ---------------
// block 256 threads, 64 rows per block in 4 passes of 16 rows.
// thread = (rrg 0..15, col 0..15).
__global__ void k_gemm2(const float* __restrict__ W, const float* __restrict__ as,
                        const float* __restrict__ ad, int n) {
    __shared__ float ws[2048];
    __shared__ float xs[16 * 128];
    int tid = threadIdx.x;
    for (int i = tid; i < 2048; i += 256) ws[i] = W[i];
    int col = tid & 15;
    int rrg = tid >> 4;
    int base = blockIdx.x * 64;
    float as_c = __ldg(&as[col]);
    float ad_c = __ldg(&ad[col]);
    int lim = n * 32;
    for (int pass = 0; pass < 4; pass++) {
        int rb = base + pass * 16;
        __syncthreads();
        for (int i = tid; i < 512; i += 256) {
            int gi = rb * 32 + i;
            ((float4*)xs)[i] = (gi < lim) ? ((const float4*)g_hl2)[gi]
                                          : make_float4(0.f, 0.f, 0.f, 0.f);
        }
        __syncthreads();
        float acc = 0.f;
#pragma unroll 8
        for (int k = 0; k < 128; k++) acc = fmaf(xs[rrg * 128 + k], ws[k * 16 + col], acc);
        float ps = acc * as_c, pd = acc * ad_c;
        ps += __shfl_xor_sync(0xffffffffu, ps, 1);
        ps += __shfl_xor_sync(0xffffffffu, ps, 2);
        ps += __shfl_xor_sync(0xffffffffu, ps, 4);
        ps += __shfl_xor_sync(0xffffffffu, ps, 8);
        pd += __shfl_xor_sync(0xffffffffu, pd, 1);
        pd += __shfl_xor_sync(0xffffffffu, pd, 2);
        pd += __shfl_xor_sync(0xffffffffu, pd, 4);
        pd += __shfl_xor_sync(0xffffffffu, pd, 8);
        int row = rb + rrg;
        if (row < n) {
            g_h2[row * 16 + col] = __float2half_rn(acc);
            if (col == 0) {
                g_als2[row] = ps;
                g_ald2[row] = pd;
            }
        }
    }
}

// ---------------- Edge pass layer2: 16 lanes per dst node --------------------
__global__ void k_edge2(const float* __restrict__ b2, float* __restrict__ out, int n) {
    int gid = blockIdx.x * blockDim.x + threadIdx.x;
    int node = gid >> 4;
    int lane = gid & 15;
    if (node >= n) return;
    float ald = g_ald2[node];
    int beg = g_off[node], end = g_off[node + 1];
    float acc = 0.f, den = 0.f;
    for (int e = beg; e < end; e++) {
        int s = g_csr[e];
        float als = g_als2[s];
        float t = als + ald;
        t = t > 0.f ? t : 0.2f * t;
        float ex = __expf(t);
        float hv = __half2float(g_h2[s * 16 + lane]);
        acc = fmaf(ex, hv, acc);
        den += ex;
    }
    out[node * 16 + lane] = fmaxf(acc / den + b2[lane], 0.f);
}

// ---------------- launch -----------------------------------------------------
extern "C" void kernel_launch(void* const* d_in, const int* in_sizes, int n_in,
                              void* d_out, int out_size) {
    const float* x     = (const float*)d_in[0];
    const int*   ei    = (const int*)d_in[1];
    const float* W1    = (const float*)d_in[2];
    const float* asrc1 = (const float*)d_in[3];
    const float* adst1 = (const float*)d_in[4];
    const float* b1    = (const float*)d_in[5];
    const float* W2    = (const float*)d_in[6];
    const float* asrc2 = (const float*)d_in[7];
    const float* adst2 = (const float*)d_in[8];
    const float* b2    = (const float*)d_in[9];

    int n = in_sizes[0] / 128;
    int E = in_sizes[1] / 2;
    const int* src = ei;
    const int* dst = ei + E;

    // CSR build (per call; static graph but must be deterministic/stateless)
    k_deginit<<<(n + 255) / 256, 256>>>(n);
    k_count<<<(E + 255) / 256, 256>>>(dst, E);
    k_scan<<<1, 1024>>>(n);
    k_scatter<<<(E + n + 255) / 256, 256>>>(src, dst, E, n);

    // layer 1
    k_gemm1<<<(n + 63) / 64, 256>>>(x, W1, asrc1, adst1, n);
    k_edge1<<<(n * 32 + 255) / 256, 256>>>(b1, n);

    // layer 2
    k_gemm2<<<(n + 63) / 64, 256>>>(W2, asrc2, adst2, n);
    k_edge2<<<(n * 16 + 255) / 256, 256>>>(b2, (float*)d_out, n);
}

// round 4
// speedup vs baseline: 1.7489x; 1.6396x over previous
#include <cstdint>
#include <cuda_runtime.h>
#include <cuda_fp16.h>

#define NMAX 50000
#define EMAX 800000
#define PAD 136   // fp16 row pitch for smem tiles (conflict-free ldmatrix)

// ---------------- device scratch --------------------------------------------
__device__ __half g_h1[NMAX * 128];
__device__ float  g_als1[NMAX * 8];
__device__ float  g_ald1[NMAX * 8];
__device__ __half g_hl2[NMAX * 128];
__device__ __half g_h2[NMAX * 16];
__device__ float  g_als2[NMAX];
__device__ float  g_ald2[NMAX];
__device__ int    g_deg[NMAX];
__device__ int    g_off[NMAX + 1];
__device__ int    g_pos[NMAX];
__device__ int    g_csr[EMAX + NMAX];
__device__ int    g_bsum[256];
__device__ int    g_bpre[256];

// ---------------- CSR build --------------------------------------------------
__global__ void k_deginit(int n) {
    int i = blockIdx.x * blockDim.x + threadIdx.x;
    if (i < n) g_deg[i] = 1;  // self loop
}

__global__ void k_count(const int* __restrict__ dst, int E) {
    int i = blockIdx.x * blockDim.x + threadIdx.x;
    if (i < E) atomicAdd(&g_deg[dst[i]], 1);
}

__global__ void k_bsum(int n) {
    __shared__ int sm[256];
    int t = threadIdx.x;
    int i = blockIdx.x * 256 + t;
    sm[t] = (i < n) ? g_deg[i] : 0;
    __syncthreads();
    for (int o = 128; o > 0; o >>= 1) {
        if (t < o) sm[t] += sm[t + o];
        __syncthreads();
    }
    if (t == 0) g_bsum[blockIdx.x] = sm[0];
}

__global__ void k_scanp(int nb, int n) {
    __shared__ int sm[256];
    int t = threadIdx.x;
    int v = (t < nb) ? g_bsum[t] : 0;
    sm[t] = v;
    __syncthreads();
    for (int o = 1; o < 256; o <<= 1) {
        int u = (t >= o) ? sm[t - o] : 0;
        __syncthreads();
        sm[t] += u;
        __syncthreads();
    }
    g_bpre[t] = sm[t] - v;
    if (t == 255) g_off[n] = sm[255];
}

__global__ void k_offsets(int n) {
    __shared__ int sm[256];
    int t = threadIdx.x;
    int i = blockIdx.x * 256 + t;
    int d = (i < n) ? g_deg[i] : 0;
    sm[t] = d;
    __syncthreads();
    for (int o = 1; o < 256; o <<= 1) {
        int u = (t >= o) ? sm[t - o] : 0;
        __syncthreads();
        sm[t] += u;
        __syncthreads();
    }
    if (i < n) {
        int off = g_bpre[blockIdx.x] + sm[t] - d;
        g_off[i] = off;
        g_pos[i] = off;
    }
}

__global__ void k_scatter(const int* __restrict__ src, const int* __restrict__ dst,
                          int E, int n) {
    int i = blockIdx.x * blockDim.x + threadIdx.x;
    if (i < E) {
        int d = dst[i];
        int p = atomicAdd(&g_pos[d], 1);
        g_csr[p] = src[i];
    } else if (i < E + n) {
        int d = i - E;
        int p = atomicAdd(&g_pos[d], 1);
        g_csr[p] = d;  // self loop
    }
}

// ---------------- GEMM1 via tensor cores (fp16 split, fp32 acc) --------------
__device__ __forceinline__ void fsplit(float f, __half& hi, __half& lo) {
    hi = __float2half_rn(f);
    lo = __float2half_rn(f - __half2float(hi));
}

__device__ __forceinline__ void ldsm4(unsigned a, unsigned* r) {
    asm volatile("ldmatrix.sync.aligned.m8n8.x4.shared.b16 {%0,%1,%2,%3}, [%4];"
                 : "=r"(r[0]), "=r"(r[1]), "=r"(r[2]), "=r"(r[3]) : "r"(a));
}
__device__ __forceinline__ void ldsm4t(unsigned a, unsigned* r) {
    asm volatile("ldmatrix.sync.aligned.m8n8.x4.trans.shared.b16 {%0,%1,%2,%3}, [%4];"
                 : "=r"(r[0]), "=r"(r[1]), "=r"(r[2]), "=r"(r[3]) : "r"(a));
}
__device__ __forceinline__ void mma16816(float* c, const unsigned* a, unsigned b0, unsigned b1) {
    asm volatile("mma.sync.aligned.m16n8k16.row.col.f32.f16.f16.f32 "
                 "{%0,%1,%2,%3},{%4,%5,%6,%7},{%8,%9},{%0,%1,%2,%3};"
                 : "+f"(c[0]), "+f"(c[1]), "+f"(c[2]), "+f"(c[3])
                 : "r"(a[0]), "r"(a[1]), "r"(a[2]), "r"(a[3]), "r"(b0), "r"(b1));
}

// block: 256 threads (8 warps as 4x2), C tile 128x128, K=128 in one shot.
__global__ void __launch_bounds__(256) k_gemm1(const float* __restrict__ x,
                                               const float* __restrict__ W, int n) {
    extern __shared__ __half sh[];
    __half* Ah = sh;
    __half* Al = Ah + 128 * PAD;
    __half* Bh = Al + 128 * PAD;
    __half* Bl = Bh + 128 * PAD;
    int tid = threadIdx.x;
    int base = blockIdx.x * 128;

    const float4* xg = (const float4*)x;
    for (int i = tid; i < 4096; i += 256) {
        int r = i >> 5, c4 = i & 31;
        int gr = base + r;
        float4 v = (gr < n) ? xg[gr * 32 + c4] : make_float4(0.f, 0.f, 0.f, 0.f);
        int cc = c4 * 4;
        __half h, l;
        fsplit(v.x, h, l); Ah[r * PAD + cc + 0] = h; Al[r * PAD + cc + 0] = l;
        fsplit(v.y, h, l); Ah[r * PAD + cc + 1] = h; Al[r * PAD + cc + 1] = l;
        fsplit(v.z, h, l); Ah[r * PAD + cc + 2] = h; Al[r * PAD + cc + 2] = l;
        fsplit(v.w, h, l); Ah[r * PAD + cc + 3] = h; Al[r * PAD + cc + 3] = l;
    }
    const float4* wg = (const float4*)W;
    for (int i = tid; i < 4096; i += 256) {
        int r = i >> 5, c4 = i & 31;
        float4 v = wg[i];
        int cc = c4 * 4;
        __half h, l;
        fsplit(v.x, h, l); Bh[r * PAD + cc + 0] = h; Bl[r * PAD + cc + 0] = l;
        fsplit(v.y, h, l); Bh[r * PAD + cc + 1] = h; Bl[r * PAD + cc + 1] = l;
        fsplit(v.z, h, l); Bh[r * PAD + cc + 2] = h; Bl[r * PAD + cc + 2] = l;
        fsplit(v.w, h, l); Bh[r * PAD + cc + 3] = h; Bl[r * PAD + cc + 3] = l;
    }
    __syncthreads();

    int warp = tid >> 5, lane = tid & 31;
    int mw = (warp >> 1) * 32;   // 4 warps along M
    int nw = (warp & 1) * 64;    // 2 warps along N
    int lr = lane & 15;
    int lk8 = (lane >> 4) * 8;

    float acc[2][8][4];
#pragma unroll
    for (int mt = 0; mt < 2; mt++)
#pragma unroll
        for (int nt = 0; nt < 8; nt++)
#pragma unroll
            for (int j = 0; j < 4; j++) acc[mt][nt][j] = 0.f;

#pragma unroll
    for (int kk = 0; kk < 8; kk++) {
        int k0 = kk * 16;
        unsigned ah[2][4], al[2][4];
#pragma unroll
        for (int mt = 0; mt < 2; mt++) {
            unsigned a = (unsigned)__cvta_generic_to_shared(
                &Ah[(mw + mt * 16 + lr) * PAD + k0 + lk8]);
            ldsm4(a, ah[mt]);
            a = (unsigned)__cvta_generic_to_shared(
                &Al[(mw + mt * 16 + lr) * PAD + k0 + lk8]);
            ldsm4(a, al[mt]);
        }
        unsigned bh[8][2], bl[8][2];
#pragma unroll
        for (int nt2 = 0; nt2 < 4; nt2++) {
            int n0 = nw + nt2 * 16;
            unsigned r4[4];
            unsigned a = (unsigned)__cvta_generic_to_shared(
                &Bh[(k0 + lr) * PAD + n0 + lk8]);
            ldsm4t(a, r4);
            bh[nt2 * 2][0] = r4[0]; bh[nt2 * 2][1] = r4[1];
            bh[nt2 * 2 + 1][0] = r4[2]; bh[nt2 * 2 + 1][1] = r4[3];
            a = (unsigned)__cvta_generic_to_shared(
                &Bl[(k0 + lr) * PAD + n0 + lk8]);
            ldsm4t(a, r4);
            bl[nt2 * 2][0] = r4[0]; bl[nt2 * 2][1] = r4[1];
            bl[nt2 * 2 + 1][0] = r4[2]; bl[nt2 * 2 + 1][1] = r4[3];
        }
#pragma unroll
        for (int mt = 0; mt < 2; mt++)
#pragma unroll
            for (int nt = 0; nt < 8; nt++) {
                mma16816(acc[mt][nt], ah[mt], bh[nt][0], bh[nt][1]);
                mma16816(acc[mt][nt], ah[mt], bl[nt][0], bl[nt][1]);
                mma16816(acc[mt][nt], al[mt], bh[nt][0], bh[nt][1]);
            }
    }

    // epilogue: store fp16 h1
    int r0 = lane >> 2, c0l = 2 * (lane & 3);
#pragma unroll
    for (int mt = 0; mt < 2; mt++)
#pragma unroll
        for (int nt = 0; nt < 8; nt++) {
            int row = base + mw + mt * 16 + r0;
            int col = nw + nt * 8 + c0l;
            if (row < n)
                ((__half2*)g_h1)[(row * 128 + col) >> 1] =
                    __floats2half2_rn(acc[mt][nt][0], acc[mt][nt][1]);
            if (row + 8 < n)
                ((__half2*)g_h1)[((row + 8) * 128 + col) >> 1] =
                    __floats2half2_rn(acc[mt][nt][2], acc[mt][nt][3]);
        }
}

// ---------------- logits layer1: warp per node -------------------------------
__global__ void k_logits1(const float* __restrict__ as, const float* __restrict__ ad,
                          int n) {
    int gid = blockIdx.x * blockDim.x + threadIdx.x;
    int node = gid >> 5, lane = gid & 31;
    if (node >= n) return;
    uint2 v = __ldg(&((const uint2*)g_h1)[node * 32 + lane]);
    float2 f0 = __half22float2(*(__half2*)&v.x);
    float2 f1 = __half22float2(*(__half2*)&v.y);
    float4 a = __ldg(&((const float4*)as)[lane]);
    float4 d = __ldg(&((const float4*)ad)[lane]);
    float ps = f0.x * a.x + f0.y * a.y + f1.x * a.z + f1.y * a.w;
    float pd = f0.x * d.x + f0.y * d.y + f1.x * d.z + f1.y * d.w;
    ps += __shfl_xor_sync(0xffffffffu, ps, 1);
    ps += __shfl_xor_sync(0xffffffffu, ps, 2);
    pd += __shfl_xor_sync(0xffffffffu, pd, 1);
    pd += __shfl_xor_sync(0xffffffffu, pd, 2);
    if ((lane & 3) == 0) {
        g_als1[node * 8 + (lane >> 2)] = ps;
        g_ald1[node * 8 + (lane >> 2)] = pd;
    }
}

// ---------------- edge pass layer1: warp per dst node, 4-deep pipelining -----
__device__ __forceinline__ void e1acc(uint2 v, float ex, float4& acc, float& den) {
    float2 fa = __half22float2(*(__half2*)&v.x);
    float2 fb = __half22float2(*(__half2*)&v.y);
    acc.x = fmaf(ex, fa.x, acc.x);
    acc.y = fmaf(ex, fa.y, acc.y);
    acc.z = fmaf(ex, fb.x, acc.z);
    acc.w = fmaf(ex, fb.y, acc.w);
    den += ex;
}
__device__ __forceinline__ float lrelu_exp(float t) {
    t = t > 0.f ? t : 0.2f * t;
    return __expf(t);
}

__global__ void k_edge1(const float* __restrict__ b1, int n) {
    int gid = blockIdx.x * blockDim.x + threadIdx.x;
    int d = gid >> 5, lane = gid & 31;
    if (d >= n) return;
    int head = lane >> 2;
    float ald = g_ald1[d * 8 + head];
    int e = g_off[d], end = g_off[d + 1];
    float4 acc = make_float4(0.f, 0.f, 0.f, 0.f);
    float den = 0.f;
    const uint2* h1v = (const uint2*)g_h1;
    for (; e + 4 <= end; e += 4) {
        int s0 = __ldg(&g_csr[e]);
        int s1 = __ldg(&g_csr[e + 1]);
        int s2 = __ldg(&g_csr[e + 2]);
        int s3 = __ldg(&g_csr[e + 3]);
        float t0 = __ldg(&g_als1[s0 * 8 + head]) + ald;
        float t1 = __ldg(&g_als1[s1 * 8 + head]) + ald;
        float t2 = __ldg(&g_als1[s2 * 8 + head]) + ald;
        float t3 = __ldg(&g_als1[s3 * 8 + head]) + ald;
        uint2 v0 = __ldg(&h1v[s0 * 32 + lane]);
        uint2 v1 = __ldg(&h1v[s1 * 32 + lane]);
        uint2 v2 = __ldg(&h1v[s2 * 32 + lane]);
        uint2 v3 = __ldg(&h1v[s3 * 32 + lane]);
        e1acc(v0, lrelu_exp(t0), acc, den);
        e1acc(v1, lrelu_exp(t1), acc, den);
        e1acc(v2, lrelu_exp(t2), acc, den);
        e1acc(v3, lrelu_exp(t3), acc, den);
    }
    for (; e < end; e++) {
        int s = __ldg(&g_csr[e]);
        float t = __ldg(&g_als1[s * 8 + head]) + ald;
        uint2 v = __ldg(&h1v[s * 32 + lane]);
        e1acc(v, lrelu_exp(t), acc, den);
    }
    float inv = 1.f / den;
    float4 b = __ldg(&((const float4*)b1)[lane]);
    __half2 o01 = __floats2half2_rn(fmaxf(acc.x * inv + b.x, 0.f),
                                    fmaxf(acc.y * inv + b.y, 0.f));
    __half2 o23 = __floats2half2_rn(fmaxf(acc.z * inv + b.z, 0.f),
                                    fmaxf(acc.w * inv + b.w, 0.f));
    uint2 u;
    u.x = *(unsigned*)&o01;
    u.y = *(unsigned*)&o23;
    ((uint2*)g_hl2)[d * 32 + lane] = u;
}

// ---------------- GEMM2: h2 = hl2(fp16) @ W2, plus logits --------------------
__global__ void k_gemm2(const float* __restrict__ W, const float* __restrict__ as,
                        const float* __restrict__ ad, int n) {
    __shared__ float ws[2048];
    __shared__ __half xs[16 * 128];
    int tid = threadIdx.x;
    for (int i = tid; i < 2048; i += 256) ws[i] = W[i];
    int col = tid & 15;
    int rrg = tid >> 4;
    int base = blockIdx.x * 64;
    float as_c = __ldg(&as[col]);
    float ad_c = __ldg(&ad[col]);
    const uint4* srcv = (const uint4*)g_hl2;  // 16 uint4 per row
    for (int pass = 0; pass < 4; pass++) {
        int rb = base + pass * 16;
        __syncthreads();
        int gi = rb * 16 + tid;
        uint4 z = make_uint4(0u, 0u, 0u, 0u);
        ((uint4*)xs)[tid] = (gi < n * 16) ? srcv[gi] : z;
        __syncthreads();
        float acc = 0.f;
        const __half2* xp = (const __half2*)&xs[rrg * 128];
#pragma unroll 16
        for (int k2 = 0; k2 < 64; k2++) {
            float2 f = __half22float2(xp[k2]);
            acc = fmaf(f.x, ws[(2 * k2) * 16 + col], acc);
            acc = fmaf(f.y, ws[(2 * k2 + 1) * 16 + col], acc);
        }
        float ps = acc * as_c, pd = acc * ad_c;
        ps += __shfl_xor_sync(0xffffffffu, ps, 1);
        ps += __shfl_xor_sync(0xffffffffu, ps, 2);
        ps += __shfl_xor_sync(0xffffffffu, ps, 4);
        ps += __shfl_xor_sync(0xffffffffu, ps, 8);
        pd += __shfl_xor_sync(0xffffffffu, pd, 1);
        pd += __shfl_xor_sync(0xffffffffu, pd, 2);
        pd += __shfl_xor_sync(0xffffffffu, pd, 4);
        pd += __shfl_xor_sync(0xffffffffu, pd, 8);
        int row = rb + rrg;
        if (row < n) {
            g_h2[row * 16 + col] = __float2half_rn(acc);
            if (col == 0) {
                g_als2[row] = ps;
                g_ald2[row] = pd;
            }
        }
    }
}

// ---------------- edge pass layer2: 16 lanes per dst node, 4-deep ------------
__global__ void k_edge2(const float* __restrict__ b2, float* __restrict__ out, int n) {
    int gid = blockIdx.x * blockDim.x + threadIdx.x;
    int node = gid >> 4, lane = gid & 15;
    if (node >= n) return;
    float ald = g_ald2[node];
    int e = g_off[node], end = g_off[node + 1];
    float acc = 0.f, den = 0.f;
    for (; e + 4 <= end; e += 4) {
        int s0 = __ldg(&g_csr[e]);
        int s1 = __ldg(&g_csr[e + 1]);
        int s2 = __ldg(&g_csr[e + 2]);
        int s3 = __ldg(&g_csr[e + 3]);
        float t0 = __ldg(&g_als2[s0]) + ald;
        float t1 = __ldg(&g_als2[s1]) + ald;
        float t2 = __ldg(&g_als2[s2]) + ald;
        float t3 = __ldg(&g_als2[s3]) + ald;
        float h0 = __half2float(g_h2[s0 * 16 + lane]);
        float h1 = __half2float(g_h2[s1 * 16 + lane]);
        float h2 = __half2float(g_h2[s2 * 16 + lane]);
        float h3 = __half2float(g_h2[s3 * 16 + lane]);
        float e0 = lrelu_exp(t0), e1 = lrelu_exp(t1);
        float e2 = lrelu_exp(t2), e3 = lrelu_exp(t3);
        acc = fmaf(e0, h0, acc); den += e0;
        acc = fmaf(e1, h1, acc); den += e1;
        acc = fmaf(e2, h2, acc); den += e2;
        acc = fmaf(e3, h3, acc); den += e3;
    }
    for (; e < end; e++) {
        int s = __ldg(&g_csr[e]);
        float t = __ldg(&g_als2[s]) + ald;
        float ex = lrelu_exp(t);
        acc = fmaf(ex, __half2float(g_h2[s * 16 + lane]), acc);
        den += ex;
    }
    out[node * 16 + lane] = fmaxf(acc / den + b2[lane], 0.f);
}

// ---------------- launch -----------------------------------------------------
extern "C" void kernel_launch(void* const* d_in, const int* in_sizes, int n_in,
                              void* d_out, int out_size) {
    const float* x     = (const float*)d_in[0];
    const int*   ei    = (const int*)d_in[1];
    const float* W1    = (const float*)d_in[2];
    const float* asrc1 = (const float*)d_in[3];
    const float* adst1 = (const float*)d_in[4];
    const float* b1    = (const float*)d_in[5];
    const float* W2    = (const float*)d_in[6];
    const float* asrc2 = (const float*)d_in[7];
    const float* adst2 = (const float*)d_in[8];
    const float* b2    = (const float*)d_in[9];

    int n = in_sizes[0] / 128;
    int E = in_sizes[1] / 2;
    const int* src = ei;
    const int* dst = ei + E;

    // CSR build
    k_deginit<<<(n + 255) / 256, 256>>>(n);
    k_count<<<(E + 255) / 256, 256>>>(dst, E);
    int nb = (n + 255) / 256;
    k_bsum<<<nb, 256>>>(n);
    k_scanp<<<1, 256>>>(nb, n);
    k_offsets<<<nb, 256>>>(n);
    k_scatter<<<(E + n + 255) / 256, 256>>>(src, dst, E, n);

    // layer 1
    const int SMEM1 = 4 * 128 * PAD * (int)sizeof(__half);  // 139264
    cudaFuncSetAttribute(k_gemm1, cudaFuncAttributeMaxDynamicSharedMemorySize, SMEM1);
    k_gemm1<<<(n + 127) / 128, 256, SMEM1>>>(x, W1, n);
    k_logits1<<<(n * 32 + 255) / 256, 256>>>(asrc1, adst1, n);
    k_edge1<<<(n * 32 + 255) / 256, 256>>>(b1, n);

    // layer 2
    k_gemm2<<<(n + 63) / 64, 256>>>(W2, asrc2, adst2, n);
    k_edge2<<<(n * 16 + 255) / 256, 256>>>(b2, (float*)d_out, n);
}

// round 5
// speedup vs baseline: 1.7774x; 1.0163x over previous
#include <cstdint>
#include <cuda_runtime.h>
#include <cuda_fp16.h>

#define NMAX 50000
#define EMAX 800000
#define PAD 136   // fp16 row pitch for smem tiles (conflict-free ldmatrix)

// ---------------- device scratch --------------------------------------------
__device__ __half g_h1[NMAX * 128];
__device__ float  g_als1[NMAX * 8];
__device__ float  g_ald1[NMAX * 8];
__device__ __half g_hl2[NMAX * 128];
__device__ __half g_h2[NMAX * 16];
__device__ float  g_als2[NMAX];
__device__ float  g_ald2[NMAX];
__device__ int    g_deg[NMAX];
__device__ int    g_off[NMAX + 1];
__device__ int    g_rank[EMAX];
__device__ int    g_csr[EMAX + NMAX];
__device__ int    g_bsum[256];
__device__ int    g_bpre[256];

// ---------------- CSR build --------------------------------------------------
__global__ void k_deginit(int n) {
    int i = blockIdx.x * blockDim.x + threadIdx.x;
    if (i < n) g_deg[i] = 1;  // self loop occupies slot 0
}

__global__ void k_count(const int* __restrict__ dst, int E) {
    int i = blockIdx.x * blockDim.x + threadIdx.x;
    if (i < E) g_rank[i] = atomicAdd(&g_deg[dst[i]], 1);  // rank within dst segment
}

__global__ void k_bsum(int n) {
    __shared__ int sm[256];
    int t = threadIdx.x;
    int i = blockIdx.x * 256 + t;
    sm[t] = (i < n) ? g_deg[i] : 0;
    __syncthreads();
    for (int o = 128; o > 0; o >>= 1) {
        if (t < o) sm[t] += sm[t + o];
        __syncthreads();
    }
    if (t == 0) g_bsum[blockIdx.x] = sm[0];
}

__global__ void k_scanp(int nb, int n) {
    __shared__ int sm[256];
    int t = threadIdx.x;
    int v = (t < nb) ? g_bsum[t] : 0;
    sm[t] = v;
    __syncthreads();
    for (int o = 1; o < 256; o <<= 1) {
        int u = (t >= o) ? sm[t - o] : 0;
        __syncthreads();
        sm[t] += u;
        __syncthreads();
    }
    g_bpre[t] = sm[t] - v;
    if (t == 255) g_off[n] = sm[255];
}

__global__ void k_offsets(int n) {
    __shared__ int sm[256];
    int t = threadIdx.x;
    int i = blockIdx.x * 256 + t;
    int d = (i < n) ? g_deg[i] : 0;
    sm[t] = d;
    __syncthreads();
    for (int o = 1; o < 256; o <<= 1) {
        int u = (t >= o) ? sm[t - o] : 0;
        __syncthreads();
        sm[t] += u;
        __syncthreads();
    }
    if (i < n) {
        int off = g_bpre[blockIdx.x] + sm[t] - d;
        g_off[i] = off;
        g_csr[off] = i;  // self loop in slot 0
    }
}

__global__ void k_scatter(const int* __restrict__ src, const int* __restrict__ dst,
                          int E) {
    int i = blockIdx.x * blockDim.x + threadIdx.x;
    if (i < E) {
        int d = dst[i];
        g_csr[g_off[d] + g_rank[i]] = src[i];  // no atomics
    }
}

// ---------------- GEMM1 via tensor cores (fp16 split, fp32 acc) --------------
__device__ __forceinline__ void ldsm4(unsigned a, unsigned* r) {
    asm volatile("ldmatrix.sync.aligned.m8n8.x4.shared.b16 {%0,%1,%2,%3}, [%4];"
                 : "=r"(r[0]), "=r"(r[1]), "=r"(r[2]), "=r"(r[3]) : "r"(a));
}
__device__ __forceinline__ void ldsm4t(unsigned a, unsigned* r) {
    asm volatile("ldmatrix.sync.aligned.m8n8.x4.trans.shared.b16 {%0,%1,%2,%3}, [%4];"
                 : "=r"(r[0]), "=r"(r[1]), "=r"(r[2]), "=r"(r[3]) : "r"(a));
}
__device__ __forceinline__ void mma16816(float* c, const unsigned* a, unsigned b0, unsigned b1) {
    asm volatile("mma.sync.aligned.m16n8k16.row.col.f32.f16.f16.f32 "
                 "{%0,%1,%2,%3},{%4,%5,%6,%7},{%8,%9},{%0,%1,%2,%3};"
                 : "+f"(c[0]), "+f"(c[1]), "+f"(c[2]), "+f"(c[3])
                 : "r"(a[0]), "r"(a[1]), "r"(a[2]), "r"(a[3]), "r"(b0), "r"(b1));
}

// split two floats into hi/lo half2 pairs
__device__ __forceinline__ void fsplit2(float f0, float f1, __half2& hi, __half2& lo) {
    hi = __floats2half2_rn(f0, f1);
    float2 h = __half22float2(hi);
    lo = __floats2half2_rn(f0 - h.x, f1 - h.y);
}

// block: 256 threads (8 warps as 4x2), C tile 128x128, K=128 in one shot.
// Epilogue also emits per-head attention logits (fused k_logits1).
__global__ void __launch_bounds__(256) k_gemm1(const float* __restrict__ x,
                                               const float* __restrict__ W,
                                               const float* __restrict__ as,
                                               const float* __restrict__ ad, int n) {
    extern __shared__ __half sh[];
    __half* Ah = sh;
    __half* Al = Ah + 128 * PAD;
    __half* Bh = Al + 128 * PAD;
    __half* Bl = Bh + 128 * PAD;
    int tid = threadIdx.x;
    int base = blockIdx.x * 128;

    const float4* xg = (const float4*)x;
    for (int i = tid; i < 4096; i += 256) {
        int r = i >> 5, c4 = i & 31;
        int gr = base + r;
        float4 v = (gr < n) ? xg[gr * 32 + c4] : make_float4(0.f, 0.f, 0.f, 0.f);
        int cc = c4 * 4;
        __half2 h, l;
        fsplit2(v.x, v.y, h, l);
        *(__half2*)&Ah[r * PAD + cc] = h;
        *(__half2*)&Al[r * PAD + cc] = l;
        fsplit2(v.z, v.w, h, l);
        *(__half2*)&Ah[r * PAD + cc + 2] = h;
        *(__half2*)&Al[r * PAD + cc + 2] = l;
    }
    const float4* wg = (const float4*)W;
    for (int i = tid; i < 4096; i += 256) {
        int r = i >> 5, c4 = i & 31;
        float4 v = wg[i];
        int cc = c4 * 4;
        __half2 h, l;
        fsplit2(v.x, v.y, h, l);
        *(__half2*)&Bh[r * PAD + cc] = h;
        *(__half2*)&Bl[r * PAD + cc] = l;
        fsplit2(v.z, v.w, h, l);
        *(__half2*)&Bh[r * PAD + cc + 2] = h;
        *(__half2*)&Bl[r * PAD + cc + 2] = l;
    }
    __syncthreads();

    int warp = tid >> 5, lane = tid & 31;
    int mw = (warp >> 1) * 32;   // 4 warps along M
    int nw = (warp & 1) * 64;    // 2 warps along N (= heads 0-3 / 4-7)
    int lr = lane & 15;
    int lk8 = (lane >> 4) * 8;

    float acc[2][8][4];
#pragma unroll
    for (int mt = 0; mt < 2; mt++)
#pragma unroll
        for (int nt = 0; nt < 8; nt++)
#pragma unroll
            for (int j = 0; j < 4; j++) acc[mt][nt][j] = 0.f;

#pragma unroll
    for (int kk = 0; kk < 8; kk++) {
        int k0 = kk * 16;
        unsigned ah[2][4], al[2][4];
#pragma unroll
        for (int mt = 0; mt < 2; mt++) {
            unsigned a = (unsigned)__cvta_generic_to_shared(
                &Ah[(mw + mt * 16 + lr) * PAD + k0 + lk8]);
            ldsm4(a, ah[mt]);
            a = (unsigned)__cvta_generic_to_shared(
                &Al[(mw + mt * 16 + lr) * PAD + k0 + lk8]);
            ldsm4(a, al[mt]);
        }
        unsigned bh[8][2], bl[8][2];
#pragma unroll
        for (int nt2 = 0; nt2 < 4; nt2++) {
            int n0 = nw + nt2 * 16;
            unsigned r4[4];
            unsigned a = (unsigned)__cvta_generic_to_shared(
                &Bh[(k0 + lr) * PAD + n0 + lk8]);
            ldsm4t(a, r4);
            bh[nt2 * 2][0] = r4[0]; bh[nt2 * 2][1] = r4[1];
            bh[nt2 * 2 + 1][0] = r4[2]; bh[nt2 * 2 + 1][1] = r4[3];
            a = (unsigned)__cvta_generic_to_shared(
                &Bl[(k0 + lr) * PAD + n0 + lk8]);
            ldsm4t(a, r4);
            bl[nt2 * 2][0] = r4[0]; bl[nt2 * 2][1] = r4[1];
            bl[nt2 * 2 + 1][0] = r4[2]; bl[nt2 * 2 + 1][1] = r4[3];
        }
#pragma unroll
        for (int mt = 0; mt < 2; mt++)
#pragma unroll
            for (int nt = 0; nt < 8; nt++) {
                mma16816(acc[mt][nt], ah[mt], bh[nt][0], bh[nt][1]);
                mma16816(acc[mt][nt], ah[mt], bl[nt][0], bl[nt][1]);
                mma16816(acc[mt][nt], al[mt], bh[nt][0], bh[nt][1]);
            }
    }

    // epilogue: store fp16 h1 + fused per-head logits
    int r0 = lane >> 2, c0l = 2 * (lane & 3);
    // load the 16 a-vector entries this thread needs (cols nw+nt*8+c0l{,+1})
    float asv[8][2], adv[8][2];
#pragma unroll
    for (int nt = 0; nt < 8; nt++) {
        int col = nw + nt * 8 + c0l;
        asv[nt][0] = __ldg(&as[col]);
        asv[nt][1] = __ldg(&as[col + 1]);
        adv[nt][0] = __ldg(&ad[col]);
        adv[nt][1] = __ldg(&ad[col + 1]);
    }
#pragma unroll
    for (int mt = 0; mt < 2; mt++) {
#pragma unroll
        for (int nt = 0; nt < 8; nt++) {
            int row = base + mw + mt * 16 + r0;
            int col = nw + nt * 8 + c0l;
            if (row < n)
                ((__half2*)g_h1)[(row * 128 + col) >> 1] =
                    __floats2half2_rn(acc[mt][nt][0], acc[mt][nt][1]);
            if (row + 8 < n)
                ((__half2*)g_h1)[((row + 8) * 128 + col) >> 1] =
                    __floats2half2_rn(acc[mt][nt][2], acc[mt][nt][3]);
        }
        // logits: head hl (local 0..3) covers tiles nt=2hl, 2hl+1 (16 cols)
#pragma unroll
        for (int hl = 0; hl < 4; hl++) {
            int t0 = 2 * hl, t1 = 2 * hl + 1;
            float ps0 = acc[mt][t0][0] * asv[t0][0] + acc[mt][t0][1] * asv[t0][1]
                      + acc[mt][t1][0] * asv[t1][0] + acc[mt][t1][1] * asv[t1][1];
            float ps1 = acc[mt][t0][2] * asv[t0][0] + acc[mt][t0][3] * asv[t0][1]
                      + acc[mt][t1][2] * asv[t1][0] + acc[mt][t1][3] * asv[t1][1];
            float pd0 = acc[mt][t0][0] * adv[t0][0] + acc[mt][t0][1] * adv[t0][1]
                      + acc[mt][t1][0] * adv[t1][0] + acc[mt][t1][1] * adv[t1][1];
            float pd1 = acc[mt][t0][2] * adv[t0][0] + acc[mt][t0][3] * adv[t0][1]
                      + acc[mt][t1][2] * adv[t1][0] + acc[mt][t1][3] * adv[t1][1];
            // reduce across the 4 lanes of the quad (same rows, different cols)
            ps0 += __shfl_xor_sync(0xffffffffu, ps0, 1);
            ps0 += __shfl_xor_sync(0xffffffffu, ps0, 2);
            ps1 += __shfl_xor_sync(0xffffffffu, ps1, 1);
            ps1 += __shfl_xor_sync(0xffffffffu, ps1, 2);
            pd0 += __shfl_xor_sync(0xffffffffu, pd0, 1);
            pd0 += __shfl_xor_sync(0xffffffffu, pd0, 2);
            pd1 += __shfl_xor_sync(0xffffffffu, pd1, 1);
            pd1 += __shfl_xor_sync(0xffffffffu, pd1, 2);
            if ((lane & 3) == 0) {
                int head = (nw >> 4) + hl;  // nw=64 -> heads 4..7
                int row = base + mw + mt * 16 + r0;
                if (row < n) {
                    g_als1[row * 8 + head] = ps0;
                    g_ald1[row * 8 + head] = pd0;
                }
                if (row + 8 < n) {
                    g_als1[(row + 8) * 8 + head] = ps1;
                    g_ald1[(row + 8) * 8 + head] = pd1;
                }
            }
        }
    }
}

// ---------------- edge pass layer1: warp per dst node, 4-deep pipelining -----
__device__ __forceinline__ void e1acc(uint2 v, float ex, float4& acc, float& den) {
    float2 fa = __half22float2(*(__half2*)&v.x);
    float2 fb = __half22float2(*(__half2*)&v.y);
    acc.x = fmaf(ex, fa.x, acc.x);
    acc.y = fmaf(ex, fa.y, acc.y);
    acc.z = fmaf(ex, fb.x, acc.z);
    acc.w = fmaf(ex, fb.y, acc.w);
    den += ex;
}
__device__ __forceinline__ float lrelu_exp(float t) {
    t = t > 0.f ? t : 0.2f * t;
    return __expf(t);
}

__global__ void k_edge1(const float* __restrict__ b1, int n) {
    int gid = blockIdx.x * blockDim.x + threadIdx.x;
    int d = gid >> 5, lane = gid & 31;
    if (d >= n) return;
    int head = lane >> 2;
    float ald = g_ald1[d * 8 + head];
    int e = g_off[d], end = g_off[d + 1];
    float4 acc = make_float4(0.f, 0.f, 0.f, 0.f);
    float den = 0.f;
    const uint2* h1v = (const uint2*)g_h1;
    for (; e + 4 <= end; e += 4) {
        int s0 = __ldg(&g_csr[e]);
        int s1 = __ldg(&g_csr[e + 1]);
        int s2 = __ldg(&g_csr[e + 2]);
        int s3 = __ldg(&g_csr[e + 3]);
        float t0 = __ldg(&g_als1[s0 * 8 + head]) + ald;
        float t1 = __ldg(&g_als1[s1 * 8 + head]) + ald;
        float t2 = __ldg(&g_als1[s2 * 8 + head]) + ald;
        float t3 = __ldg(&g_als1[s3 * 8 + head]) + ald;
        uint2 v0 = __ldg(&h1v[s0 * 32 + lane]);
        uint2 v1 = __ldg(&h1v[s1 * 32 + lane]);
        uint2 v2 = __ldg(&h1v[s2 * 32 + lane]);
        uint2 v3 = __ldg(&h1v[s3 * 32 + lane]);
        e1acc(v0, lrelu_exp(t0), acc, den);
        e1acc(v1, lrelu_exp(t1), acc, den);
        e1acc(v2, lrelu_exp(t2), acc, den);
        e1acc(v3, lrelu_exp(t3), acc, den);
    }
    for (; e < end; e++) {
        int s = __ldg(&g_csr[e]);
        float t = __ldg(&g_als1[s * 8 + head]) + ald;
        uint2 v = __ldg(&h1v[s * 32 + lane]);
        e1acc(v, lrelu_exp(t), acc, den);
    }
    float inv = 1.f / den;
    float4 b = __ldg(&((const float4*)b1)[lane]);
    __half2 o01 = __floats2half2_rn(fmaxf(acc.x * inv + b.x, 0.f),
                                    fmaxf(acc.y * inv + b.y, 0.f));
    __half2 o23 = __floats2half2_rn(fmaxf(acc.z * inv + b.z, 0.f),
                                    fmaxf(acc.w * inv + b.w, 0.f));
    uint2 u;
    u.x = *(unsigned*)&o01;
    u.y = *(unsigned*)&o23;
    ((uint2*)g_hl2)[d * 32 + lane] = u;
}

// ---------------- GEMM2: h2 = hl2(fp16) @ W2, plus logits --------------------
__global__ void k_gemm2(const float* __restrict__ W, const float* __restrict__ as,
                        const float* __restrict__ ad, int n) {
    __shared__ float ws[2048];
    __shared__ __half xs[16 * 128];
    int tid = threadIdx.x;
    for (int i = tid; i < 2048; i += 256) ws[i] = W[i];
    int col = tid & 15;
    int rrg = tid >> 4;
    int base = blockIdx.x * 64;
    float as_c = __ldg(&as[col]);
    float ad_c = __ldg(&ad[col]);
    const uint4* srcv = (const uint4*)g_hl2;  // 16 uint4 per row
    for (int pass = 0; pass < 4; pass++) {
        int rb = base + pass * 16;
        __syncthreads();
        int gi = rb * 16 + tid;
        uint4 z = make_uint4(0u, 0u, 0u, 0u);
        ((uint4*)xs)[tid] = (gi < n * 16) ? srcv[gi] : z;
        __syncthreads();
        float acc = 0.f;
        const __half2* xp = (const __half2*)&xs[rrg * 128];
#pragma unroll 16
        for (int k2 = 0; k2 < 64; k2++) {
            float2 f = __half22float2(xp[k2]);
            acc = fmaf(f.x, ws[(2 * k2) * 16 + col], acc);
            acc = fmaf(f.y, ws[(2 * k2 + 1) * 16 + col], acc);
        }
        float ps = acc * as_c, pd = acc * ad_c;
        ps += __shfl_xor_sync(0xffffffffu, ps, 1);
        ps += __shfl_xor_sync(0xffffffffu, ps, 2);
        ps += __shfl_xor_sync(0xffffffffu, ps, 4);
        ps += __shfl_xor_sync(0xffffffffu, ps, 8);
        pd += __shfl_xor_sync(0xffffffffu, pd, 1);
        pd += __shfl_xor_sync(0xffffffffu, pd, 2);
        pd += __shfl_xor_sync(0xffffffffu, pd, 4);
        pd += __shfl_xor_sync(0xffffffffu, pd, 8);
        int row = rb + rrg;
        if (row < n) {
            g_h2[row * 16 + col] = __float2half_rn(acc);
            if (col == 0) {
                g_als2[row] = ps;
                g_ald2[row] = pd;
            }
        }
    }
}

// ---------------- edge pass layer2: 16 lanes per dst node, 4-deep ------------
__global__ void k_edge2(const float* __restrict__ b2, float* __restrict__ out, int n) {
    int gid = blockIdx.x * blockDim.x + threadIdx.x;
    int node = gid >> 4, lane = gid & 15;
    if (node >= n) return;
    float ald = g_ald2[node];
    int e = g_off[node], end = g_off[node + 1];
    float acc = 0.f, den = 0.f;
    for (; e + 4 <= end; e += 4) {
        int s0 = __ldg(&g_csr[e]);
        int s1 = __ldg(&g_csr[e + 1]);
        int s2 = __ldg(&g_csr[e + 2]);
        int s3 = __ldg(&g_csr[e + 3]);
        float t0 = __ldg(&g_als2[s0]) + ald;
        float t1 = __ldg(&g_als2[s1]) + ald;
        float t2 = __ldg(&g_als2[s2]) + ald;
        float t3 = __ldg(&g_als2[s3]) + ald;
        float h0 = __half2float(g_h2[s0 * 16 + lane]);
        float h1 = __half2float(g_h2[s1 * 16 + lane]);
        float h2 = __half2float(g_h2[s2 * 16 + lane]);
        float h3 = __half2float(g_h2[s3 * 16 + lane]);
        float e0 = lrelu_exp(t0), e1 = lrelu_exp(t1);
        float e2 = lrelu_exp(t2), e3 = lrelu_exp(t3);
        acc = fmaf(e0, h0, acc); den += e0;
        acc = fmaf(e1, h1, acc); den += e1;
        acc = fmaf(e2, h2, acc); den += e2;
        acc = fmaf(e3, h3, acc); den += e3;
    }
    for (; e < end; e++) {
        int s = __ldg(&g_csr[e]);
        float t = __ldg(&g_als2[s]) + ald;
        float ex = lrelu_exp(t);
        acc = fmaf(ex, __half2float(g_h2[s * 16 + lane]), acc);
        den += ex;
    }
    out[node * 16 + lane] = fmaxf(acc / den + b2[lane], 0.f);
}

// ---------------- launch -----------------------------------------------------
extern "C" void kernel_launch(void* const* d_in, const int* in_sizes, int n_in,
                              void* d_out, int out_size) {
    const float* x     = (const float*)d_in[0];
    const int*   ei    = (const int*)d_in[1];
    const float* W1    = (const float*)d_in[2];
    const float* asrc1 = (const float*)d_in[3];
    const float* adst1 = (const float*)d_in[4];
    const float* b1    = (const float*)d_in[5];
    const float* W2    = (const float*)d_in[6];
    const float* asrc2 = (const float*)d_in[7];
    const float* adst2 = (const float*)d_in[8];
    const float* b2    = (const float*)d_in[9];

    int n = in_sizes[0] / 128;
    int E = in_sizes[1] / 2;
    const int* src = ei;
    const int* dst = ei + E;

    // CSR build
    k_deginit<<<(n + 255) / 256, 256>>>(n);
    k_count<<<(E + 255) / 256, 256>>>(dst, E);
    int nb = (n + 255) / 256;
    k_bsum<<<nb, 256>>>(n);
    k_scanp<<<1, 256>>>(nb, n);
    k_offsets<<<nb, 256>>>(n);
    k_scatter<<<(E + 255) / 256, 256>>>(src, dst, E);

    // layer 1 (logits fused into gemm1 epilogue)
    const int SMEM1 = 4 * 128 * PAD * (int)sizeof(__half);  // 139264
    cudaFuncSetAttribute(k_gemm1, cudaFuncAttributeMaxDynamicSharedMemorySize, SMEM1);
    k_gemm1<<<(n + 127) / 128, 256, SMEM1>>>(x, W1, asrc1, adst1, n);
    k_edge1<<<(n * 32 + 255) / 256, 256>>>(b1, n);

    // layer 2
    k_gemm2<<<(n + 63) / 64, 256>>>(W2, asrc2, adst2, n);
    k_edge2<<<(n * 16 + 255) / 256, 256>>>(b2, (float*)d_out, n);
}

// round 6
// speedup vs baseline: 1.8576x; 1.0451x over previous
#include <cstdint>
#include <cuda_runtime.h>
#include <cuda_fp16.h>

#define NMAX 50000
#define EMAX 800000
#define PAD 136   // fp16 row pitch for smem tiles (conflict-free ldmatrix)

// ---------------- device scratch --------------------------------------------
__device__ __half g_h1[NMAX * 128];
__device__ float  g_als1[NMAX * 8];
__device__ float  g_ald1[NMAX * 8];
__device__ __half g_hl2[NMAX * 128];
__device__ __half g_h2[NMAX * 16];
__device__ float  g_als2[NMAX];
__device__ float  g_ald2[NMAX];
__device__ int    g_deg[NMAX];
__device__ int    g_off[NMAX + 1];
__device__ int    g_rank[EMAX];
__device__ int    g_csr[EMAX + NMAX];
__device__ int    g_bsum[256];

// ---------------- CSR build --------------------------------------------------
__global__ void k_deginit(int n) {
    int i = blockIdx.x * blockDim.x + threadIdx.x;
    if (i < n) g_deg[i] = 1;  // self loop occupies slot 0
}

__global__ void k_count(const int* __restrict__ dst, int E) {
    int i = blockIdx.x * blockDim.x + threadIdx.x;
    if (i < E) g_rank[i] = atomicAdd(&g_deg[dst[i]], 1);  // rank within dst segment
}

__global__ void k_bsum(int n) {
    __shared__ int sm[256];
    int t = threadIdx.x;
    int i = blockIdx.x * 256 + t;
    sm[t] = (i < n) ? g_deg[i] : 0;
    __syncthreads();
    for (int o = 128; o > 0; o >>= 1) {
        if (t < o) sm[t] += sm[t + o];
        __syncthreads();
    }
    if (t == 0) g_bsum[blockIdx.x] = sm[0];
}

// fused: every block scans the (<=256) block sums locally, then scans its own
// 256 degrees and writes offsets + self-loop slot. Removes the single-block
// k_scanp launch from the serial chain.
__global__ void k_offsets(int nb, int n) {
    __shared__ int sb[256];
    __shared__ int sm[256];
    int t = threadIdx.x;
    sb[t] = (t < nb) ? g_bsum[t] : 0;
    __syncthreads();
    for (int o = 1; o < 256; o <<= 1) {
        int u = (t >= o) ? sb[t - o] : 0;
        __syncthreads();
        sb[t] += u;
        __syncthreads();
    }
    int bpre = (blockIdx.x == 0) ? 0 : sb[blockIdx.x - 1];
    if (blockIdx.x == 0 && t == 255) g_off[n] = sb[255];
    int i = blockIdx.x * 256 + t;
    int d = (i < n) ? g_deg[i] : 0;
    sm[t] = d;
    __syncthreads();
    for (int o = 1; o < 256; o <<= 1) {
        int u = (t >= o) ? sm[t - o] : 0;
        __syncthreads();
        sm[t] += u;
        __syncthreads();
    }
    if (i < n) {
        int off = bpre + sm[t] - d;
        g_off[i] = off;
        g_csr[off] = i;  // self loop in slot 0
    }
}

__global__ void k_scatter(const int* __restrict__ src, const int* __restrict__ dst,
                          int E) {
    int i = blockIdx.x * blockDim.x + threadIdx.x;
    if (i < E) {
        int d = dst[i];
        g_csr[g_off[d] + g_rank[i]] = src[i];  // no atomics
    }
}

// ---------------- GEMM1 via tensor cores (fp16 split, fp32 acc) --------------
__device__ __forceinline__ void ldsm4(unsigned a, unsigned* r) {
    asm volatile("ldmatrix.sync.aligned.m8n8.x4.shared.b16 {%0,%1,%2,%3}, [%4];"
                 : "=r"(r[0]), "=r"(r[1]), "=r"(r[2]), "=r"(r[3]) : "r"(a));
}
__device__ __forceinline__ void ldsm4t(unsigned a, unsigned* r) {
    asm volatile("ldmatrix.sync.aligned.m8n8.x4.trans.shared.b16 {%0,%1,%2,%3}, [%4];"
                 : "=r"(r[0]), "=r"(r[1]), "=r"(r[2]), "=r"(r[3]) : "r"(a));
}
__device__ __forceinline__ void mma16816(float* c, const unsigned* a, unsigned b0, unsigned b1) {
    asm volatile("mma.sync.aligned.m16n8k16.row.col.f32.f16.f16.f32 "
                 "{%0,%1,%2,%3},{%4,%5,%6,%7},{%8,%9},{%0,%1,%2,%3};"
                 : "+f"(c[0]), "+f"(c[1]), "+f"(c[2]), "+f"(c[3])
                 : "r"(a[0]), "r"(a[1]), "r"(a[2]), "r"(a[3]), "r"(b0), "r"(b1));
}

__device__ __forceinline__ void fsplit2(float f0, float f1, __half2& hi, __half2& lo) {
    hi = __floats2half2_rn(f0, f1);
    float2 h = __half22float2(hi);
    lo = __floats2half2_rn(f0 - h.x, f1 - h.y);
}

// block: 256 threads (8 warps as 4x2), C tile 128x128, K=128 in one shot.
// Epilogue also emits per-head attention logits.
__global__ void __launch_bounds__(256) k_gemm1(const float* __restrict__ x,
                                               const float* __restrict__ W,
                                               const float* __restrict__ as,
                                               const float* __restrict__ ad, int n) {
    extern __shared__ __half sh[];
    __half* Ah = sh;
    __half* Al = Ah + 128 * PAD;
    __half* Bh = Al + 128 * PAD;
    __half* Bl = Bh + 128 * PAD;
    int tid = threadIdx.x;
    int base = blockIdx.x * 128;

    const float4* xg = (const float4*)x;
    for (int i = tid; i < 4096; i += 256) {
        int r = i >> 5, c4 = i & 31;
        int gr = base + r;
        float4 v = (gr < n) ? xg[gr * 32 + c4] : make_float4(0.f, 0.f, 0.f, 0.f);
        int cc = c4 * 4;
        __half2 h, l;
        fsplit2(v.x, v.y, h, l);
        *(__half2*)&Ah[r * PAD + cc] = h;
        *(__half2*)&Al[r * PAD + cc] = l;
        fsplit2(v.z, v.w, h, l);
        *(__half2*)&Ah[r * PAD + cc + 2] = h;
        *(__half2*)&Al[r * PAD + cc + 2] = l;
    }
    const float4* wg = (const float4*)W;
    for (int i = tid; i < 4096; i += 256) {
        int r = i >> 5, c4 = i & 31;
        float4 v = wg[i];
        int cc = c4 * 4;
        __half2 h, l;
        fsplit2(v.x, v.y, h, l);
        *(__half2*)&Bh[r * PAD + cc] = h;
        *(__half2*)&Bl[r * PAD + cc] = l;
        fsplit2(v.z, v.w, h, l);
        *(__half2*)&Bh[r * PAD + cc + 2] = h;
        *(__half2*)&Bl[r * PAD + cc + 2] = l;
    }
    __syncthreads();

    int warp = tid >> 5, lane = tid & 31;
    int mw = (warp >> 1) * 32;   // 4 warps along M
    int nw = (warp & 1) * 64;    // 2 warps along N (= heads 0-3 / 4-7)
    int lr = lane & 15;
    int lk8 = (lane >> 4) * 8;

    float acc[2][8][4];
#pragma unroll
    for (int mt = 0; mt < 2; mt++)
#pragma unroll
        for (int nt = 0; nt < 8; nt++)
#pragma unroll
            for (int j = 0; j < 4; j++) acc[mt][nt][j] = 0.f;

#pragma unroll
    for (int kk = 0; kk < 8; kk++) {
        int k0 = kk * 16;
        unsigned ah[2][4], al[2][4];
#pragma unroll
        for (int mt = 0; mt < 2; mt++) {
            unsigned a = (unsigned)__cvta_generic_to_shared(
                &Ah[(mw + mt * 16 + lr) * PAD + k0 + lk8]);
            ldsm4(a, ah[mt]);
            a = (unsigned)__cvta_generic_to_shared(
                &Al[(mw + mt * 16 + lr) * PAD + k0 + lk8]);
            ldsm4(a, al[mt]);
        }
        unsigned bh[8][2], bl[8][2];
#pragma unroll
        for (int nt2 = 0; nt2 < 4; nt2++) {
            int n0 = nw + nt2 * 16;
            unsigned r4[4];
            unsigned a = (unsigned)__cvta_generic_to_shared(
                &Bh[(k0 + lr) * PAD + n0 + lk8]);
            ldsm4t(a, r4);
            bh[nt2 * 2][0] = r4[0]; bh[nt2 * 2][1] = r4[1];
            bh[nt2 * 2 + 1][0] = r4[2]; bh[nt2 * 2 + 1][1] = r4[3];
            a = (unsigned)__cvta_generic_to_shared(
                &Bl[(k0 + lr) * PAD + n0 + lk8]);
            ldsm4t(a, r4);
            bl[nt2 * 2][0] = r4[0]; bl[nt2 * 2][1] = r4[1];
            bl[nt2 * 2 + 1][0] = r4[2]; bl[nt2 * 2 + 1][1] = r4[3];
        }
#pragma unroll
        for (int mt = 0; mt < 2; mt++)
#pragma unroll
            for (int nt = 0; nt < 8; nt++) {
                mma16816(acc[mt][nt], ah[mt], bh[nt][0], bh[nt][1]);
                mma16816(acc[mt][nt], ah[mt], bl[nt][0], bl[nt][1]);
                mma16816(acc[mt][nt], al[mt], bh[nt][0], bh[nt][1]);
            }
    }

    // epilogue: store fp16 h1 + fused per-head logits
    int r0 = lane >> 2, c0l = 2 * (lane & 3);
    float asv[8][2], adv[8][2];
#pragma unroll
    for (int nt = 0; nt < 8; nt++) {
        int col = nw + nt * 8 + c0l;
        asv[nt][0] = __ldg(&as[col]);
        asv[nt][1] = __ldg(&as[col + 1]);
        adv[nt][0] = __ldg(&ad[col]);
        adv[nt][1] = __ldg(&ad[col + 1]);
    }
#pragma unroll
    for (int mt = 0; mt < 2; mt++) {
#pragma unroll
        for (int nt = 0; nt < 8; nt++) {
            int row = base + mw + mt * 16 + r0;
            int col = nw + nt * 8 + c0l;
            if (row < n)
                ((__half2*)g_h1)[(row * 128 + col) >> 1] =
                    __floats2half2_rn(acc[mt][nt][0], acc[mt][nt][1]);
            if (row + 8 < n)
                ((__half2*)g_h1)[((row + 8) * 128 + col) >> 1] =
                    __floats2half2_rn(acc[mt][nt][2], acc[mt][nt][3]);
        }
#pragma unroll
        for (int hl = 0; hl < 4; hl++) {
            int t0 = 2 * hl, t1 = 2 * hl + 1;
            float ps0 = acc[mt][t0][0] * asv[t0][0] + acc[mt][t0][1] * asv[t0][1]
                      + acc[mt][t1][0] * asv[t1][0] + acc[mt][t1][1] * asv[t1][1];
            float ps1 = acc[mt][t0][2] * asv[t0][0] + acc[mt][t0][3] * asv[t0][1]
                      + acc[mt][t1][2] * asv[t1][0] + acc[mt][t1][3] * asv[t1][1];
            float pd0 = acc[mt][t0][0] * adv[t0][0] + acc[mt][t0][1] * adv[t0][1]
                      + acc[mt][t1][0] * adv[t1][0] + acc[mt][t1][1] * adv[t1][1];
            float pd1 = acc[mt][t0][2] * adv[t0][0] + acc[mt][t0][3] * adv[t0][1]
                      + acc[mt][t1][2] * adv[t1][0] + acc[mt][t1][3] * adv[t1][1];
            ps0 += __shfl_xor_sync(0xffffffffu, ps0, 1);
            ps0 += __shfl_xor_sync(0xffffffffu, ps0, 2);
            ps1 += __shfl_xor_sync(0xffffffffu, ps1, 1);
            ps1 += __shfl_xor_sync(0xffffffffu, ps1, 2);
            pd0 += __shfl_xor_sync(0xffffffffu, pd0, 1);
            pd0 += __shfl_xor_sync(0xffffffffu, pd0, 2);
            pd1 += __shfl_xor_sync(0xffffffffu, pd1, 1);
            pd1 += __shfl_xor_sync(0xffffffffu, pd1, 2);
            if ((lane & 3) == 0) {
                int head = (nw >> 4) + hl;
                int row = base + mw + mt * 16 + r0;
                if (row < n) {
                    g_als1[row * 8 + head] = ps0;
                    g_ald1[row * 8 + head] = pd0;
                }
                if (row + 8 < n) {
                    g_als1[(row + 8) * 8 + head] = ps1;
                    g_ald1[(row + 8) * 8 + head] = pd1;
                }
            }
        }
    }
}

// ---------------- edge pass layer1: warp per dst node, 8-deep pipelining -----
__device__ __forceinline__ void e1acc(uint2 v, float ex, float4& acc, float& den) {
    float2 fa = __half22float2(*(__half2*)&v.x);
    float2 fb = __half22float2(*(__half2*)&v.y);
    acc.x = fmaf(ex, fa.x, acc.x);
    acc.y = fmaf(ex, fa.y, acc.y);
    acc.z = fmaf(ex, fb.x, acc.z);
    acc.w = fmaf(ex, fb.y, acc.w);
    den += ex;
}
__device__ __forceinline__ float lrelu_exp(float t) {
    t = t > 0.f ? t : 0.2f * t;
    return __expf(t);
}

__global__ void k_edge1(const float* __restrict__ b1, int n) {
    int gid = blockIdx.x * blockDim.x + threadIdx.x;
    int d = gid >> 5, lane = gid & 31;
    if (d >= n) return;
    int head = lane >> 2;
    float ald = g_ald1[d * 8 + head];
    int e = g_off[d], end = g_off[d + 1];
    float4 acc = make_float4(0.f, 0.f, 0.f, 0.f);
    float den = 0.f;
    const uint2* h1v = (const uint2*)g_h1;
    for (; e + 8 <= end; e += 8) {
        int s[8];
        float t[8];
        uint2 v[8];
#pragma unroll
        for (int j = 0; j < 8; j++) s[j] = __ldg(&g_csr[e + j]);
#pragma unroll
        for (int j = 0; j < 8; j++) t[j] = __ldg(&g_als1[s[j] * 8 + head]) + ald;
#pragma unroll
        for (int j = 0; j < 8; j++) v[j] = __ldg(&h1v[s[j] * 32 + lane]);
#pragma unroll
        for (int j = 0; j < 8; j++) e1acc(v[j], lrelu_exp(t[j]), acc, den);
    }
    for (; e + 4 <= end; e += 4) {
        int s0 = __ldg(&g_csr[e]);
        int s1 = __ldg(&g_csr[e + 1]);
        int s2 = __ldg(&g_csr[e + 2]);
        int s3 = __ldg(&g_csr[e + 3]);
        float t0 = __ldg(&g_als1[s0 * 8 + head]) + ald;
        float t1 = __ldg(&g_als1[s1 * 8 + head]) + ald;
        float t2 = __ldg(&g_als1[s2 * 8 + head]) + ald;
        float t3 = __ldg(&g_als1[s3 * 8 + head]) + ald;
        uint2 v0 = __ldg(&h1v[s0 * 32 + lane]);
        uint2 v1 = __ldg(&h1v[s1 * 32 + lane]);
        uint2 v2 = __ldg(&h1v[s2 * 32 + lane]);
        uint2 v3 = __ldg(&h1v[s3 * 32 + lane]);
        e1acc(v0, lrelu_exp(t0), acc, den);
        e1acc(v1, lrelu_exp(t1), acc, den);
        e1acc(v2, lrelu_exp(t2), acc, den);
        e1acc(v3, lrelu_exp(t3), acc, den);
    }
    for (; e < end; e++) {
        int s = __ldg(&g_csr[e]);
        float t = __ldg(&g_als1[s * 8 + head]) + ald;
        uint2 v = __ldg(&h1v[s * 32 + lane]);
        e1acc(v, lrelu_exp(t), acc, den);
    }
    float inv = 1.f / den;
    float4 b = __ldg(&((const float4*)b1)[lane]);
    __half2 o01 = __floats2half2_rn(fmaxf(acc.x * inv + b.x, 0.f),
                                    fmaxf(acc.y * inv + b.y, 0.f));
    __half2 o23 = __floats2half2_rn(fmaxf(acc.z * inv + b.z, 0.f),
                                    fmaxf(acc.w * inv + b.w, 0.f));
    uint2 u;
    u.x = *(unsigned*)&o01;
    u.y = *(unsigned*)&o23;
    ((uint2*)g_hl2)[d * 32 + lane] = u;
}

// ---------------- GEMM2: h2 = hl2(fp16) @ W2, plus logits --------------------
__global__ void k_gemm2(const float* __restrict__ W, const float* __restrict__ as,
                        const float* __restrict__ ad, int n) {
    __shared__ float ws[2048];
    __shared__ __half xs[16 * 128];
    int tid = threadIdx.x;
    for (int i = tid; i < 2048; i += 256) ws[i] = W[i];
    int col = tid & 15;
    int rrg = tid >> 4;
    int base = blockIdx.x * 64;
    float as_c = __ldg(&as[col]);
    float ad_c = __ldg(&ad[col]);
    const uint4* srcv = (const uint4*)g_hl2;
    for (int pass = 0; pass < 4; pass++) {
        int rb = base + pass * 16;
        __syncthreads();
        int gi = rb * 16 + tid;
        uint4 z = make_uint4(0u, 0u, 0u, 0u);
        ((uint4*)xs)[tid] = (gi < n * 16) ? srcv[gi] : z;
        __syncthreads();
        float acc = 0.f;
        const __half2* xp = (const __half2*)&xs[rrg * 128];
#pragma unroll 16
        for (int k2 = 0; k2 < 64; k2++) {
            float2 f = __half22float2(xp[k2]);
            acc = fmaf(f.x, ws[(2 * k2) * 16 + col], acc);
            acc = fmaf(f.y, ws[(2 * k2 + 1) * 16 + col], acc);
        }
        float ps = acc * as_c, pd = acc * ad_c;
        ps += __shfl_xor_sync(0xffffffffu, ps, 1);
        ps += __shfl_xor_sync(0xffffffffu, ps, 2);
        ps += __shfl_xor_sync(0xffffffffu, ps, 4);
        ps += __shfl_xor_sync(0xffffffffu, ps, 8);
        pd += __shfl_xor_sync(0xffffffffu, pd, 1);
        pd += __shfl_xor_sync(0xffffffffu, pd, 2);
        pd += __shfl_xor_sync(0xffffffffu, pd, 4);
        pd += __shfl_xor_sync(0xffffffffu, pd, 8);
        int row = rb + rrg;
        if (row < n) {
            g_h2[row * 16 + col] = __float2half_rn(acc);
            if (col == 0) {
                g_als2[row] = ps;
                g_ald2[row] = pd;
            }
        }
    }
}

// ---------------- edge pass layer2: 16 lanes per dst node, 4-deep ------------
__global__ void k_edge2(const float* __restrict__ b2, float* __restrict__ out, int n) {
    int gid = blockIdx.x * blockDim.x + threadIdx.x;
    int node = gid >> 4, lane = gid & 15;
    if (node >= n) return;
    float ald = g_ald2[node];
    int e = g_off[node], end = g_off[node + 1];
    float acc = 0.f, den = 0.f;
    for (; e + 4 <= end; e += 4) {
        int s0 = __ldg(&g_csr[e]);
        int s1 = __ldg(&g_csr[e + 1]);
        int s2 = __ldg(&g_csr[e + 2]);
        int s3 = __ldg(&g_csr[e + 3]);
        float t0 = __ldg(&g_als2[s0]) + ald;
        float t1 = __ldg(&g_als2[s1]) + ald;
        float t2 = __ldg(&g_als2[s2]) + ald;
        float t3 = __ldg(&g_als2[s3]) + ald;
        float h0 = __half2float(g_h2[s0 * 16 + lane]);
        float h1 = __half2float(g_h2[s1 * 16 + lane]);
        float h2 = __half2float(g_h2[s2 * 16 + lane]);
        float h3 = __half2float(g_h2[s3 * 16 + lane]);
        float e0 = lrelu_exp(t0), e1 = lrelu_exp(t1);
        float e2 = lrelu_exp(t2), e3 = lrelu_exp(t3);
        acc = fmaf(e0, h0, acc); den += e0;
        acc = fmaf(e1, h1, acc); den += e1;
        acc = fmaf(e2, h2, acc); den += e2;
        acc = fmaf(e3, h3, acc); den += e3;
    }
    for (; e < end; e++) {
        int s = __ldg(&g_csr[e]);
        float t = __ldg(&g_als2[s]) + ald;
        float ex = lrelu_exp(t);
        acc = fmaf(ex, __half2float(g_h2[s * 16 + lane]), acc);
        den += ex;
    }
    out[node * 16 + lane] = fmaxf(acc / den + b2[lane], 0.f);
}

// ---------------- launch -----------------------------------------------------
extern "C" void kernel_launch(void* const* d_in, const int* in_sizes, int n_in,
                              void* d_out, int out_size) {
    const float* x     = (const float*)d_in[0];
    const int*   ei    = (const int*)d_in[1];
    const float* W1    = (const float*)d_in[2];
    const float* asrc1 = (const float*)d_in[3];
    const float* adst1 = (const float*)d_in[4];
    const float* b1    = (const float*)d_in[5];
    const float* W2    = (const float*)d_in[6];
    const float* asrc2 = (const float*)d_in[7];
    const float* adst2 = (const float*)d_in[8];
    const float* b2    = (const float*)d_in[9];

    int n = in_sizes[0] / 128;
    int E = in_sizes[1] / 2;
    const int* src = ei;
    const int* dst = ei + E;
    int nb = (n + 255) / 256;

    // fork a side stream: CSR build runs concurrently with GEMM1
    cudaStream_t s2;
    cudaStreamCreateWithFlags(&s2, cudaStreamNonBlocking);
    cudaEvent_t evFork, evJoin;
    cudaEventCreateWithFlags(&evFork, cudaEventDisableTiming);
    cudaEventCreateWithFlags(&evJoin, cudaEventDisableTiming);

    cudaEventRecord(evFork, 0);
    cudaStreamWaitEvent(s2, evFork, 0);

    // CSR build chain on s2
    k_deginit<<<nb, 256, 0, s2>>>(n);
    k_count<<<(E + 255) / 256, 256, 0, s2>>>(dst, E);
    k_bsum<<<nb, 256, 0, s2>>>(n);
    k_offsets<<<nb, 256, 0, s2>>>(nb, n);
    k_scatter<<<(E + 255) / 256, 256, 0, s2>>>(src, dst, E);
    cudaEventRecord(evJoin, s2);

    // GEMM1 (with fused logits) on the main stream, concurrent with CSR build
    const int SMEM1 = 4 * 128 * PAD * (int)sizeof(__half);  // 139264
    cudaFuncSetAttribute(k_gemm1, cudaFuncAttributeMaxDynamicSharedMemorySize, SMEM1);
    k_gemm1<<<(n + 127) / 128, 256, SMEM1>>>(x, W1, asrc1, adst1, n);

    // join: edge1 needs both CSR and gemm1
    cudaStreamWaitEvent((cudaStream_t)0, evJoin, 0);
    k_edge1<<<(n * 32 + 255) / 256, 256>>>(b1, n);

    // layer 2
    k_gemm2<<<(n + 63) / 64, 256>>>(W2, asrc2, adst2, n);
    k_edge2<<<(n * 16 + 255) / 256, 256>>>(b2, (float*)d_out, n);

    cudaEventDestroy(evFork);
    cudaEventDestroy(evJoin);
    cudaStreamDestroy(s2);
}